// round 15
// baseline (speedup 1.0000x reference)
#include <cuda_runtime.h>
#include <cuda_bf16.h>
#include <cstdint>
#include <math.h>

#define NB 2
#define NT 2048
#define NC 1024
#define NH 16
#define DH 64
#define NM (NB*NT)   // 4096 rows
#define NBH (NB*NH)  // 32

// ---------------------------------------------------------------------------
// Scratch (__device__ globals; zero-initialized, no allocations)
// ---------------------------------------------------------------------------
__device__ float g_Q[(size_t)NM*NC];
__device__ float g_K[(size_t)NM*NC];
__device__ float g_V[(size_t)NM*NC];
__device__ float g_Y[(size_t)NM*NC];
// Q pack [bh][t][64] bf16 hi/lo (pre-scaled by 0.125)
__device__ unsigned short g_Qbh[(size_t)NBH*NT*DH];
__device__ unsigned short g_Qbl[(size_t)NBH*NT*DH];
// K fragment pack: idx = ((bh*256 + k8)*4 + kc)*32 + lane   [uint2]
__device__ uint2 g_KFh[(size_t)NBH*256*4*32];
__device__ uint2 g_KFl[(size_t)NBH*256*4*32];
// V fragment pack: idx = ((bh*8 + nv)*128 + jj)*32 + lane   [uint2]
__device__ uint2 g_VFh[(size_t)NBH*8*128*32];
__device__ uint2 g_VFl[(size_t)NBH*8*128*32];
// Projection A-frag pack: idx = (R*64 + c)*32 + lane        [uint4]
__device__ uint4 g_PAh[(size_t)(NM/16)*(NC/16)*32];
__device__ uint4 g_PAl[(size_t)(NM/16)*(NC/16)*32];
// Projection B-frag pack: idx = ((z*128 + n8)*64 + c)*32 + lane  [uint2]
__device__ uint2 g_PBh[(size_t)4*128*64*32];
__device__ uint2 g_PBl[(size_t)4*128*64*32];
// check scratch
__device__ float g_cm[8*16];
__device__ float g_cl[8*16];
__device__ float g_cacc[8*16*64];
__device__ int g_badF;   // tensor flash failed verification
__device__ int g_badP;   // tensor projection failed verification

// ---------------------------------------------------------------------------
// Helpers
// ---------------------------------------------------------------------------
__device__ __forceinline__ void mma_bf16(float* d, const uint32_t* a, const uint32_t* b) {
    asm volatile("mma.sync.aligned.m16n8k16.row.col.f32.bf16.bf16.f32 "
        "{%0,%1,%2,%3}, {%4,%5,%6,%7}, {%8,%9}, {%0,%1,%2,%3};"
        : "+f"(d[0]), "+f"(d[1]), "+f"(d[2]), "+f"(d[3])
        : "r"(a[0]), "r"(a[1]), "r"(a[2]), "r"(a[3]), "r"(b[0]), "r"(b[1]));
}
__device__ __forceinline__ void bsplit(float x, unsigned short& h, unsigned short& l) {
    __nv_bfloat16 bh = __float2bfloat16(x);
    float fh = __bfloat162float(bh);
    __nv_bfloat16 bl = __float2bfloat16(x - fh);
    h = __bfloat16_as_ushort(bh);
    l = __bfloat16_as_ushort(bl);
}
// pack two floats (low elem -> low 16 bits) into bf16x2 hi word + lo word
__device__ __forceinline__ uint32_t packP(float a, float b, uint32_t& lo) {
    unsigned short ha, la, hb, lb;
    bsplit(a, ha, la);
    bsplit(b, hb, lb);
    lo = (uint32_t)la | ((uint32_t)lb << 16);
    return (uint32_t)ha | ((uint32_t)hb << 16);
}

// ---------------------------------------------------------------------------
__global__ void zero_flag_kernel() { g_badF = 0; g_badP = 0; }

// ===========================================================================
// PROJECTION TENSOR PATH
// ===========================================================================

// A-fragment pack: in[NM, NC] -> g_PAh/g_PAl (R8 word order).
// src = 0: in = x (external); src = 1: in = g_Y.
__global__ __launch_bounds__(256)
void pafrag_kernel(const float* __restrict__ xin, int src)
{
    const float* in = (src == 0) ? xin : g_Y;
    int idx = blockIdx.x * 256 + threadIdx.x;
    int lane = idx & 31;
    int Rc = idx >> 5;
    int c = Rc & 63, R = Rc >> 6;
    int g = lane >> 2, t = lane & 3;
    int r0 = R * 16 + g;
    int k0 = c * 16 + 2 * t;
    const float* p = in + (size_t)r0 * NC + k0;
    uint4 H, L;
    H.x = packP(p[0],          p[1],          L.x);
    H.y = packP(p[8 * NC],     p[8 * NC + 1], L.y);
    H.z = packP(p[8],          p[9],          L.z);
    H.w = packP(p[8 * NC + 8], p[8 * NC + 9], L.w);
    g_PAh[idx] = H;
    g_PAl[idx] = L;
}

// B-fragment pack: W[K,N] (z = 0..3: Wq,Wk,Wv,Wo) -> g_PBh/g_PBl.
__global__ __launch_bounds__(256)
void pbfrag_kernel(const float* __restrict__ Wq, const float* __restrict__ Wk,
                   const float* __restrict__ Wv, const float* __restrict__ Wo)
{
    int idx = blockIdx.x * 256 + threadIdx.x;
    int lane = idx & 31;
    int c = (idx >> 5) & 63;
    int n8 = (idx >> 11) & 127;
    int z = idx >> 18;
    const float* W = (z == 0) ? Wq : (z == 1) ? Wk : (z == 2) ? Wv : Wo;
    int g = lane >> 2, t = lane & 3;
    int n = n8 * 8 + g;
    int k0 = c * 16 + 2 * t;
    uint2 H, L;
    H.x = packP(W[(size_t)k0 * NC + n],       W[(size_t)(k0 + 1) * NC + n], L.x);
    H.y = packP(W[(size_t)(k0 + 8) * NC + n], W[(size_t)(k0 + 9) * NC + n], L.y);
    g_PBh[idx] = H;
    g_PBl[idx] = L;
}

// Fragment-packed bf16 GEMM. 256 thr = 8 warps; warp w -> 32 rows
// (two 16-row groups). Block covers 256 rows x 64 cols.
// mode 0: z in {0,1,2} -> g_Q/g_K/g_V; mode 1: z = 3 -> Cext (d_out).
// gate=1: run only if g_badP == 0.
__global__ __launch_bounds__(256)
void pgemm_kernel(const float* __restrict__ bq, const float* __restrict__ bk,
                  const float* __restrict__ bv, const float* __restrict__ bo,
                  float* __restrict__ Cext, int mode, int gate)
{
    if (gate && g_badP != 0) return;
    int tid = threadIdx.x, w = tid >> 5, lane = tid & 31;
    int g8 = lane >> 2, t4 = lane & 3;
    int n0 = blockIdx.x * 64, m0 = blockIdx.y * 256;
    int z = (mode == 0) ? blockIdx.z : 3;
    const float* bias = (mode == 0) ? ((z == 0) ? bq : (z == 1) ? bk : bv) : bo;
    float* C = (mode == 0) ? ((z == 0) ? g_Q : (z == 1) ? g_K : g_V) : Cext;

    int R0 = (m0 >> 4) + w * 2;            // two consecutive 16-row groups
    const uint4* Ah0 = g_PAh + (size_t)R0 * 2048 + lane;
    const uint4* Al0 = g_PAl + (size_t)R0 * 2048 + lane;
    const uint4* Ah1 = g_PAh + (size_t)(R0 + 1) * 2048 + lane;
    const uint4* Al1 = g_PAl + (size_t)(R0 + 1) * 2048 + lane;
    const uint2* Bh = g_PBh + ((size_t)z * 128 + blockIdx.x * 8) * 2048 + lane;
    const uint2* Bl = g_PBl + ((size_t)z * 128 + blockIdx.x * 8) * 2048 + lane;

    float acc[2][8][4];
#pragma unroll
    for (int mf = 0; mf < 2; mf++)
#pragma unroll
        for (int nf = 0; nf < 8; nf++)
#pragma unroll
            for (int q = 0; q < 4; q++) acc[mf][nf][q] = 0.0f;

    for (int c = 0; c < 64; c++) {
        uint4 a4h0 = Ah0[c * 32];
        uint4 a4l0 = Al0[c * 32];
        uint4 a4h1 = Ah1[c * 32];
        uint4 a4l1 = Al1[c * 32];
        uint32_t ah[2][4], al[2][4];
        ah[0][0] = a4h0.x; ah[0][1] = a4h0.y; ah[0][2] = a4h0.z; ah[0][3] = a4h0.w;
        al[0][0] = a4l0.x; al[0][1] = a4l0.y; al[0][2] = a4l0.z; al[0][3] = a4l0.w;
        ah[1][0] = a4h1.x; ah[1][1] = a4h1.y; ah[1][2] = a4h1.z; ah[1][3] = a4h1.w;
        al[1][0] = a4l1.x; al[1][1] = a4l1.y; al[1][2] = a4l1.z; al[1][3] = a4l1.w;
#pragma unroll
        for (int nf = 0; nf < 8; nf++) {
            uint2 b2h = Bh[(size_t)nf * 2048 + c * 32];
            uint2 b2l = Bl[(size_t)nf * 2048 + c * 32];
            uint32_t bh[2], bl[2];
            bh[0] = b2h.x; bh[1] = b2h.y;
            bl[0] = b2l.x; bl[1] = b2l.y;
#pragma unroll
            for (int mf = 0; mf < 2; mf++) {
                mma_bf16(acc[mf][nf], ah[mf], bh);
                mma_bf16(acc[mf][nf], al[mf], bh);
                mma_bf16(acc[mf][nf], ah[mf], bl);
            }
        }
    }

#pragma unroll
    for (int mf = 0; mf < 2; mf++) {
        int mrow = m0 + (w * 2 + mf) * 16 + g8;
#pragma unroll
        for (int nf = 0; nf < 8; nf++) {
            int col = n0 + nf * 8 + t4 * 2;
            float2 b2 = *(const float2*)(bias + col);
            float2 o;
            o.x = acc[mf][nf][0] + b2.x; o.y = acc[mf][nf][1] + b2.y;
            *(float2*)(C + (size_t)mrow * NC + col) = o;
            o.x = acc[mf][nf][2] + b2.x; o.y = acc[mf][nf][3] + b2.y;
            *(float2*)(C + (size_t)(mrow + 8) * NC + col) = o;
        }
    }
}

// Projection check: recompute a 32x128 tile in fp32 and compare.
__global__ __launch_bounds__(256)
void pcheck_kernel(const float* __restrict__ x, const float* __restrict__ W,
                   const float* __restrict__ b, int which)
{
    int idx = blockIdx.x * 256 + threadIdx.x;   // 0..4095
    int r = idx >> 7, c = idx & 127;
    const float* xr = x + (size_t)r * NC;
    float s = 0.0f;
#pragma unroll 4
    for (int k = 0; k < NC; k++)
        s += xr[k] * W[(size_t)k * NC + c];
    s += b[c];
    const float* Cq = (which == 0) ? g_Q : (which == 1) ? g_K : g_V;
    float q = Cq[(size_t)r * NC + c];
    if (fabsf(q - s) > 0.02f * (fabsf(s) + 0.5f))
        atomicExch(&g_badP, 1);
}

// ===========================================================================
// FLASH TENSOR PATH
// ===========================================================================

__global__ __launch_bounds__(256)
void pack_q_kernel()
{
    int id = blockIdx.x * 256 + threadIdx.x;
    int d4 = id & 15;
    int t = (id >> 4) & (NT - 1);
    int bh = id >> 15;
    int b = bh >> 4, h = bh & 15;
    size_t src = ((size_t)(b * NT + t)) * NC + h * DH + d4 * 4;
    size_t dst = ((size_t)bh * NT + t) * DH + d4 * 4;
    float4 q = *(const float4*)(g_Q + src);
    ushort4 qh, ql;
    bsplit(q.x * 0.125f, qh.x, ql.x);
    bsplit(q.y * 0.125f, qh.y, ql.y);
    bsplit(q.z * 0.125f, qh.z, ql.z);
    bsplit(q.w * 0.125f, qh.w, ql.w);
    *(ushort4*)(g_Qbh + dst) = qh;
    *(ushort4*)(g_Qbl + dst) = ql;
}

__global__ __launch_bounds__(256)
void kfrag_kernel()
{
    int id = blockIdx.x * 256 + threadIdx.x;
    int lane = id & 31;
    int kc = (id >> 5) & 3;
    int k8 = (id >> 7) & 255;
    int bh = id >> 15;
    int b = bh >> 4, h = bh & 15;
    int g8 = lane >> 2, t4 = lane & 3;
    int key = k8 * 8 + g8;
    int d0 = kc * 16 + 2 * t4;
    const float* p = g_K + ((size_t)(b * NT + key)) * NC + h * DH + d0;
    uint2 H, L;
    H.x = packP(p[0], p[1], L.x);
    H.y = packP(p[8], p[9], L.y);
    g_KFh[id] = H;
    g_KFl[id] = L;
}

__global__ __launch_bounds__(256)
void vfrag_kernel()
{
    int id = blockIdx.x * 256 + threadIdx.x;
    int lane = id & 31;
    int jj = (id >> 5) & 127;
    int nv = (id >> 12) & 7;
    int bh = id >> 15;
    int b = bh >> 4, h = bh & 15;
    int g8 = lane >> 2, t4 = lane & 3;
    int d = nv * 8 + g8;
    int key0 = jj * 16 + 2 * t4;
    const float* base = g_V + (size_t)b * NT * NC + h * DH + d;
    uint2 H, L;
    H.x = packP(base[(size_t)key0 * NC],       base[(size_t)(key0 + 1) * NC], L.x);
    H.y = packP(base[(size_t)(key0 + 8) * NC], base[(size_t)(key0 + 9) * NC], L.y);
    g_VFh[id] = H;
    g_VFl[id] = L;
}

// Tensor flash, 64-key chunks (half the softmax fixed cost per key).
__global__ __launch_bounds__(128)
void flash_mma_kernel()
{
    int tid = threadIdx.x, w = tid >> 5, lane = tid & 31;
    int g8 = lane >> 2, t4 = lane & 3;
    int qt = blockIdx.x, bh = blockIdx.y;

    const unsigned short* Qh = g_Qbh + ((size_t)bh * NT + qt * 64 + w * 16) * DH;
    const unsigned short* Ql = g_Qbl + ((size_t)bh * NT + qt * 64 + w * 16) * DH;
    uint32_t qfh[4][4], qfl[4][4];
#pragma unroll
    for (int kc = 0; kc < 4; kc++) {
        int d0 = kc * 16 + 2 * t4;
        qfh[kc][0] = *(const uint32_t*)(Qh + (size_t)g8 * DH + d0);
        qfh[kc][1] = *(const uint32_t*)(Qh + (size_t)(g8 + 8) * DH + d0);
        qfh[kc][2] = *(const uint32_t*)(Qh + (size_t)g8 * DH + d0 + 8);
        qfh[kc][3] = *(const uint32_t*)(Qh + (size_t)(g8 + 8) * DH + d0 + 8);
        qfl[kc][0] = *(const uint32_t*)(Ql + (size_t)g8 * DH + d0);
        qfl[kc][1] = *(const uint32_t*)(Ql + (size_t)(g8 + 8) * DH + d0);
        qfl[kc][2] = *(const uint32_t*)(Ql + (size_t)g8 * DH + d0 + 8);
        qfl[kc][3] = *(const uint32_t*)(Ql + (size_t)(g8 + 8) * DH + d0 + 8);
    }

    const uint2* KFh = g_KFh + (size_t)bh * 32768 + lane;
    const uint2* KFl = g_KFl + (size_t)bh * 32768 + lane;
    const uint2* VFh = g_VFh + (size_t)bh * 32768 + lane;
    const uint2* VFl = g_VFl + (size_t)bh * 32768 + lane;

    float o[8][4];
#pragma unroll
    for (int nv = 0; nv < 8; nv++)
#pragma unroll
        for (int q = 0; q < 4; q++) o[nv][q] = 0.0f;
    float m0 = -1e30f, m1 = -1e30f, l0 = 0.0f, l1 = 0.0f;

    for (int k0 = 0; k0 < NT; k0 += 64) {
        int k8b = k0 >> 3;
        // ---- S = Q K^T  (16 x 64) ----
        float s[8][4];
#pragma unroll
        for (int nf = 0; nf < 8; nf++)
#pragma unroll
            for (int q = 0; q < 4; q++) s[nf][q] = 0.0f;
#pragma unroll
        for (int nf = 0; nf < 8; nf++) {
            size_t kb = (size_t)(k8b + nf) * 128;
#pragma unroll
            for (int kc = 0; kc < 4; kc++) {
                uint2 kh = KFh[kb + kc * 32];
                uint2 kl = KFl[kb + kc * 32];
                uint32_t bhh[2], bll[2];
                bhh[0] = kh.x; bhh[1] = kh.y;
                bll[0] = kl.x; bll[1] = kl.y;
                mma_bf16(s[nf], qfh[kc], bhh);
                mma_bf16(s[nf], qfl[kc], bhh);
                mma_bf16(s[nf], qfh[kc], bll);
            }
        }

        // ---- online softmax, row-set 0 (rows g8) on c0,c1 ----
        {
            float rm = s[0][0];
#pragma unroll
            for (int nf = 0; nf < 8; nf++) {
                rm = fmaxf(rm, s[nf][0]);
                rm = fmaxf(rm, s[nf][1]);
            }
            rm = fmaxf(rm, __shfl_xor_sync(0xffffffffu, rm, 1));
            rm = fmaxf(rm, __shfl_xor_sync(0xffffffffu, rm, 2));
            float mn = fmaxf(m0, rm);
            float corr = __expf(m0 - mn);
            float rs = 0.0f;
#pragma unroll
            for (int nf = 0; nf < 8; nf++) {
                s[nf][0] = __expf(s[nf][0] - mn);
                s[nf][1] = __expf(s[nf][1] - mn);
                rs += s[nf][0] + s[nf][1];
            }
            rs += __shfl_xor_sync(0xffffffffu, rs, 1);
            rs += __shfl_xor_sync(0xffffffffu, rs, 2);
            l0 = l0 * corr + rs;
            m0 = mn;
#pragma unroll
            for (int nv = 0; nv < 8; nv++) {
                o[nv][0] *= corr;
                o[nv][1] *= corr;
            }
        }
        // ---- row-set 1 (rows g8+8) on c2,c3 ----
        {
            float rm = s[0][2];
#pragma unroll
            for (int nf = 0; nf < 8; nf++) {
                rm = fmaxf(rm, s[nf][2]);
                rm = fmaxf(rm, s[nf][3]);
            }
            rm = fmaxf(rm, __shfl_xor_sync(0xffffffffu, rm, 1));
            rm = fmaxf(rm, __shfl_xor_sync(0xffffffffu, rm, 2));
            float mn = fmaxf(m1, rm);
            float corr = __expf(m1 - mn);
            float rs = 0.0f;
#pragma unroll
            for (int nf = 0; nf < 8; nf++) {
                s[nf][2] = __expf(s[nf][2] - mn);
                s[nf][3] = __expf(s[nf][3] - mn);
                rs += s[nf][2] + s[nf][3];
            }
            rs += __shfl_xor_sync(0xffffffffu, rs, 1);
            rs += __shfl_xor_sync(0xffffffffu, rs, 2);
            l1 = l1 * corr + rs;
            m1 = mn;
#pragma unroll
            for (int nv = 0; nv < 8; nv++) {
                o[nv][2] *= corr;
                o[nv][3] *= corr;
            }
        }

        // ---- O += P V  (4 k-chunks of 16 keys) ----
#pragma unroll
        for (int j = 0; j < 4; j++) {
            uint32_t ph[4], pl[4];
            ph[0] = packP(s[2 * j][0],     s[2 * j][1],     pl[0]);
            ph[1] = packP(s[2 * j][2],     s[2 * j][3],     pl[1]);
            ph[2] = packP(s[2 * j + 1][0], s[2 * j + 1][1], pl[2]);
            ph[3] = packP(s[2 * j + 1][2], s[2 * j + 1][3], pl[3]);
            int jbase = (k0 >> 4) + j;
#pragma unroll
            for (int nv = 0; nv < 8; nv++) {
                uint2 vh = VFh[((size_t)nv * 128 + jbase) * 32];
                uint2 vl = VFl[((size_t)nv * 128 + jbase) * 32];
                uint32_t bvh[2], bvl[2];
                bvh[0] = vh.x; bvh[1] = vh.y;
                bvl[0] = vl.x; bvl[1] = vl.y;
                mma_bf16(o[nv], ph, bvh);
                mma_bf16(o[nv], pl, bvh);
                mma_bf16(o[nv], ph, bvl);
            }
        }
    }

    float inv0 = 1.0f / l0, inv1 = 1.0f / l1;
    int b = bh >> 4, h = bh & 15;
    size_t row0 = (size_t)b * NT + qt * 64 + w * 16 + g8;
#pragma unroll
    for (int nv = 0; nv < 8; nv++) {
        int col = h * DH + nv * 8 + t4 * 2;
        float2 v;
        v.x = o[nv][0] * inv0; v.y = o[nv][1] * inv0;
        *(float2*)(g_Y + row0 * NC + col) = v;
        v.x = o[nv][2] * inv1; v.y = o[nv][3] * inv1;
        *(float2*)(g_Y + (row0 + 8) * NC + col) = v;
    }
}

__global__ __launch_bounds__(128)
void fcheck1_kernel()
{
    int sl = blockIdx.x;
    int tid = threadIdx.x;
    int r = tid >> 4, c = tid & 15;
    const float* Qr = g_Q + (size_t)r * NC;
    float m = -1e30f, l = 0.0f;
    float acc[4] = {0.0f, 0.0f, 0.0f, 0.0f};

    for (int key = sl * 128; key < sl * 128 + 128; key++) {
        const float* Kr = g_K + (size_t)key * NC;
        float part = 0.0f;
#pragma unroll
        for (int dd = 0; dd < 4; dd++) part += Qr[c * 4 + dd] * Kr[c * 4 + dd];
        part += __shfl_xor_sync(0xffffffffu, part, 1);
        part += __shfl_xor_sync(0xffffffffu, part, 2);
        part += __shfl_xor_sync(0xffffffffu, part, 4);
        part += __shfl_xor_sync(0xffffffffu, part, 8);
        float sc = part * 0.125f;
        float mn = fmaxf(m, sc);
        float corr = __expf(m - mn);
        float p = __expf(sc - mn);
        l = l * corr + p;
        const float* Vr = g_V + (size_t)key * NC;
#pragma unroll
        for (int dd = 0; dd < 4; dd++)
            acc[dd] = acc[dd] * corr + p * Vr[c * 4 + dd];
        m = mn;
    }
    if (c == 0) { g_cm[r * 16 + sl] = m; g_cl[r * 16 + sl] = l; }
#pragma unroll
    for (int dd = 0; dd < 4; dd++)
        g_cacc[(r * 16 + sl) * 64 + c * 4 + dd] = acc[dd];
}

__global__ __launch_bounds__(512)
void fcheck2_kernel()
{
    int tid = threadIdx.x;
    int r = tid >> 6, d = tid & 63;
    float M = -1e30f;
#pragma unroll
    for (int sl = 0; sl < 16; sl++) M = fmaxf(M, g_cm[r * 16 + sl]);
    float L = 0.0f, A = 0.0f;
#pragma unroll
    for (int sl = 0; sl < 16; sl++) {
        float e = __expf(g_cm[r * 16 + sl] - M);
        L += g_cl[r * 16 + sl] * e;
        A += g_cacc[(r * 16 + sl) * 64 + d] * e;
    }
    float y = A / L;
    float got = g_Y[(size_t)r * NC + d];
    if (fabsf(got - y) > 0.02f * fabsf(y) + 0.01f)
        atomicExch(&g_badF, 1);
}

// ===========================================================================
// FP32 FALLBACKS (proven R1 kernels, gated)
// ===========================================================================
#define GBM 128
#define GBN 128
#define GBK 8

__global__ __launch_bounds__(256)
void sgemm_bias_kernel(const float* __restrict__ Aext,
                       const float* __restrict__ W0, const float* __restrict__ W1,
                       const float* __restrict__ W2,
                       const float* __restrict__ b0, const float* __restrict__ b1,
                       const float* __restrict__ b2,
                       float* __restrict__ Cext, int mode)
{
    if (g_badP == 0) return;

    const int N = NC, K = NC;
    const float* A; const float* W; const float* bias; float* C;
    int z = blockIdx.z;
    if (mode == 0) {
        A = Aext;
        W    = (z == 0) ? W0 : (z == 1) ? W1 : W2;
        bias = (z == 0) ? b0 : (z == 1) ? b1 : b2;
        C    = (z == 0) ? g_Q : (z == 1) ? g_K : g_V;
    } else {
        A = g_Y; W = W0; bias = b0; C = Cext;
    }

    __shared__ float As[GBK][GBM];
    __shared__ float Bs[GBK][GBN];

    int tid = threadIdx.x;
    int bx = blockIdx.x, by = blockIdx.y;

    float acc[8][8];
#pragma unroll
    for (int i = 0; i < 8; i++)
#pragma unroll
        for (int j = 0; j < 8; j++) acc[i][j] = 0.0f;

    const float* Ab = A + (size_t)by * GBM * K;
    const float* Wb = W + (size_t)bx * GBN;

    int arow = tid >> 1, acol = (tid & 1) * 4;
    int brow = tid >> 5, bcol = (tid & 31) * 4;
    int rg = (tid >> 4) * 8;
    int cg = (tid & 15) * 8;

    for (int kt = 0; kt < K; kt += GBK) {
        float4 av = *(const float4*)(Ab + (size_t)arow * K + kt + acol);
        float4 bv = *(const float4*)(Wb + (size_t)(kt + brow) * N + bcol);
        __syncthreads();
        As[acol + 0][arow] = av.x;
        As[acol + 1][arow] = av.y;
        As[acol + 2][arow] = av.z;
        As[acol + 3][arow] = av.w;
        *(float4*)&Bs[brow][bcol] = bv;
        __syncthreads();
#pragma unroll
        for (int k = 0; k < GBK; k++) {
            float ra[8], rb[8];
            *(float4*)&ra[0] = *(const float4*)&As[k][rg];
            *(float4*)&ra[4] = *(const float4*)&As[k][rg + 4];
            *(float4*)&rb[0] = *(const float4*)&Bs[k][cg];
            *(float4*)&rb[4] = *(const float4*)&Bs[k][cg + 4];
#pragma unroll
            for (int i = 0; i < 8; i++)
#pragma unroll
                for (int j = 0; j < 8; j++)
                    acc[i][j] += ra[i] * rb[j];
        }
    }

    size_t row0 = (size_t)by * GBM + rg;
    int col0 = bx * GBN + cg;
#pragma unroll
    for (int i = 0; i < 8; i++) {
#pragma unroll
        for (int j = 0; j < 8; j += 4) {
            float4 o;
            o.x = acc[i][j + 0] + bias[col0 + j + 0];
            o.y = acc[i][j + 1] + bias[col0 + j + 1];
            o.z = acc[i][j + 2] + bias[col0 + j + 2];
            o.w = acc[i][j + 3] + bias[col0 + j + 3];
            *(float4*)(C + (row0 + i) * N + col0 + j) = o;
        }
    }
}

#define FBQ 64
#define FBK 32
#define QP 65
#define KP 66
#define SP 33

__global__ __launch_bounds__(128)
void flash_fp32_kernel()
{
    if (g_badF == 0) return;

    __shared__ float Qs[FBQ][QP];
    __shared__ float KS[2112];
    __shared__ float Vs[FBK][DH];

    int tid = threadIdx.x;
    int qt = blockIdx.x;
    int bh = blockIdx.y;
    int b = bh >> 4, h = bh & 15;

    const float* Qg = g_Q + (size_t)b * NT * NC + h * DH;
    const float* Kg = g_K + (size_t)b * NT * NC + h * DH;
    const float* Vg = g_V + (size_t)b * NT * NC + h * DH;

    int ty = tid >> 3;
    int tx = tid & 7;
    int ty4 = ty * 4;

    {
        int lq = tid >> 4;
        int d  = (tid & 15) * 4;
#pragma unroll
        for (int r = 0; r < 8; r++) {
            int q = lq + r * 8;
            float4 v = *(const float4*)(Qg + (size_t)(qt * FBQ + q) * NC + d);
            Qs[q][d + 0] = v.x * 0.125f;
            Qs[q][d + 1] = v.y * 0.125f;
            Qs[q][d + 2] = v.z * 0.125f;
            Qs[q][d + 3] = v.w * 0.125f;
        }
    }

    float oa[4][8];
    float m_r[4], l_r[4];
#pragma unroll
    for (int i = 0; i < 4; i++) {
        m_r[i] = -1e30f; l_r[i] = 0.0f;
#pragma unroll
        for (int c = 0; c < 8; c++) oa[i][c] = 0.0f;
    }

    for (int kt = 0; kt < NT / FBK; kt++) {
        const float* Kt = Kg + (size_t)(kt * FBK) * NC;
        const float* Vt = Vg + (size_t)(kt * FBK) * NC;

        __syncthreads();
        {
            int lk = tid >> 4;
            int d  = (tid & 15) * 4;
#pragma unroll
            for (int r = 0; r < 4; r++) {
                int key = lk + r * 8;
                float4 kv = *(const float4*)(Kt + (size_t)key * NC + d);
                float* Kp = &KS[key * KP + d];
                Kp[0] = kv.x; Kp[1] = kv.y; Kp[2] = kv.z; Kp[3] = kv.w;
                float4 vv = *(const float4*)(Vt + (size_t)key * NC + d);
                *(float4*)&Vs[key][d] = vv;
            }
        }
        __syncthreads();

        float s[4][4];
#pragma unroll
        for (int i = 0; i < 4; i++)
#pragma unroll
            for (int j = 0; j < 4; j++) s[i][j] = 0.0f;

#pragma unroll 4
        for (int d = 0; d < DH; d++) {
            float rq[4], rk[4];
#pragma unroll
            for (int i = 0; i < 4; i++) rq[i] = Qs[ty4 + i][d];
#pragma unroll
            for (int j = 0; j < 4; j++) rk[j] = KS[(tx + 8 * j) * KP + d];
#pragma unroll
            for (int i = 0; i < 4; i++)
#pragma unroll
                for (int j = 0; j < 4; j++)
                    s[i][j] += rq[i] * rk[j];
        }
        __syncthreads();

        float p[4][4], corr[4], rsum[4];
#pragma unroll
        for (int i = 0; i < 4; i++) {
            float tm = fmaxf(fmaxf(s[i][0], s[i][1]), fmaxf(s[i][2], s[i][3]));
            tm = fmaxf(tm, __shfl_xor_sync(0xffffffffu, tm, 1));
            tm = fmaxf(tm, __shfl_xor_sync(0xffffffffu, tm, 2));
            tm = fmaxf(tm, __shfl_xor_sync(0xffffffffu, tm, 4));
            float mnew = fmaxf(m_r[i], tm);
            corr[i] = __expf(m_r[i] - mnew);
            float rs = 0.0f;
#pragma unroll
            for (int j = 0; j < 4; j++) {
                p[i][j] = __expf(s[i][j] - mnew);
                rs += p[i][j];
            }
            rs += __shfl_xor_sync(0xffffffffu, rs, 1);
            rs += __shfl_xor_sync(0xffffffffu, rs, 2);
            rs += __shfl_xor_sync(0xffffffffu, rs, 4);
            rsum[i] = rs;
            m_r[i] = mnew;
        }
#pragma unroll
        for (int i = 0; i < 4; i++) {
            l_r[i] = l_r[i] * corr[i] + rsum[i];
#pragma unroll
            for (int c = 0; c < 8; c++) oa[i][c] *= corr[i];
        }

#pragma unroll
        for (int i = 0; i < 4; i++)
#pragma unroll
            for (int j = 0; j < 4; j++)
                KS[(ty4 + i) * SP + (tx + 8 * j)] = p[i][j];
        __syncthreads();

#pragma unroll 4
        for (int k = 0; k < FBK; k++) {
            float rs[4];
#pragma unroll
            for (int i = 0; i < 4; i++) rs[i] = KS[(ty4 + i) * SP + k];
            float4 v0 = *(const float4*)&Vs[k][tx * 8];
            float4 v1 = *(const float4*)&Vs[k][tx * 8 + 4];
#pragma unroll
            for (int i = 0; i < 4; i++) {
                oa[i][0] += rs[i] * v0.x;
                oa[i][1] += rs[i] * v0.y;
                oa[i][2] += rs[i] * v0.z;
                oa[i][3] += rs[i] * v0.w;
                oa[i][4] += rs[i] * v1.x;
                oa[i][5] += rs[i] * v1.y;
                oa[i][6] += rs[i] * v1.z;
                oa[i][7] += rs[i] * v1.w;
            }
        }
    }

#pragma unroll
    for (int i = 0; i < 4; i++) {
        float inv = 1.0f / l_r[i];
        size_t row = (size_t)b * NT + qt * FBQ + ty4 + i;
        float* Yp = g_Y + row * NC + h * DH + tx * 8;
        float4 o0, o1;
        o0.x = oa[i][0] * inv; o0.y = oa[i][1] * inv;
        o0.z = oa[i][2] * inv; o0.w = oa[i][3] * inv;
        o1.x = oa[i][4] * inv; o1.y = oa[i][5] * inv;
        o1.z = oa[i][6] * inv; o1.w = oa[i][7] * inv;
        *(float4*)Yp = o0;
        *(float4*)(Yp + 4) = o1;
    }
}

// ---------------------------------------------------------------------------
extern "C" void kernel_launch(void* const* d_in, const int* in_sizes, int n_in,
                              void* d_out, int out_size)
{
    const float* x  = (const float*)d_in[0];
    const float* Wq = (const float*)d_in[1];
    const float* bq = (const float*)d_in[2];
    const float* Wk = (const float*)d_in[3];
    const float* bk = (const float*)d_in[4];
    const float* Wv = (const float*)d_in[5];
    const float* bv = (const float*)d_in[6];
    const float* Wo = (const float*)d_in[7];
    const float* bo = (const float*)d_in[8];
    float* out = (float*)d_out;

    // 0) reset flags
    zero_flag_kernel<<<1, 1>>>();
    // 1) projection fragment packs (x + all weights)
    pafrag_kernel<<<(NM / 16) * (NC / 16) * 32 / 256, 256>>>(x, 0);
    pbfrag_kernel<<<4 * 128 * 64 * 32 / 256, 256>>>(Wq, Wk, Wv, Wo);
    // 2) tensor QKV projections (256 rows/block)
    pgemm_kernel<<<dim3(NC / 64, NM / 256, 3), 256>>>(
        bq, bk, bv, bo, nullptr, 0, 0);
    // 3) verify Q, K, V tiles
    pcheck_kernel<<<16, 256>>>(x, Wq, bq, 0);
    pcheck_kernel<<<16, 256>>>(x, Wk, bk, 1);
    pcheck_kernel<<<16, 256>>>(x, Wv, bv, 2);
    // 4) fp32 fallback QKV (no-op when verified)
    sgemm_bias_kernel<<<dim3(NC / GBN, NM / GBM, 3), 256>>>(
        x, Wq, Wk, Wv, bq, bk, bv, nullptr, 0);
    // 5) flash packs + tensor flash
    pack_q_kernel<<<4096, 256>>>();
    kfrag_kernel<<<4096, 256>>>();
    vfrag_kernel<<<4096, 256>>>();
    flash_mma_kernel<<<dim3(NT / 64, NBH), 128>>>();
    // 6) flash verification + fp32 fallback
    fcheck1_kernel<<<16, 128>>>();
    fcheck2_kernel<<<1, 512>>>();
    flash_fp32_kernel<<<dim3(NT / FBQ, NBH), 128>>>();
    // 7) out-projection: pack Y, tensor gemm (gated) / fp32 fallback
    pafrag_kernel<<<(NM / 16) * (NC / 16) * 32 / 256, 256>>>(x, 1);
    pgemm_kernel<<<dim3(NC / 64, NM / 256, 1), 256>>>(
        bq, bk, bv, bo, out, 1, 1);
    sgemm_bias_kernel<<<dim3(NC / GBN, NM / GBM, 1), 256>>>(
        x, Wo, nullptr, nullptr, bo, nullptr, nullptr, out, 1);
}

// round 16
// speedup vs baseline: 1.2412x; 1.2412x over previous
#include <cuda_runtime.h>
#include <cuda_bf16.h>
#include <cstdint>
#include <math.h>

#define NB 2
#define NT 2048
#define NC 1024
#define NH 16
#define DH 64
#define NM (NB*NT)   // 4096 rows
#define NBH (NB*NH)  // 32

// ---------------------------------------------------------------------------
// Scratch (__device__ globals; zero-initialized, no allocations)
// ---------------------------------------------------------------------------
__device__ float g_Q[(size_t)NM*NC];
__device__ float g_K[(size_t)NM*NC];
__device__ float g_V[(size_t)NM*NC];
__device__ float g_Y[(size_t)NM*NC];
// Q pack [bh][t][64] bf16 hi/lo (pre-scaled by 0.125)
__device__ unsigned short g_Qbh[(size_t)NBH*NT*DH];
__device__ unsigned short g_Qbl[(size_t)NBH*NT*DH];
// K fragment pack: idx = ((bh*256 + k8)*4 + kc)*32 + lane   [uint2]
__device__ uint2 g_KFh[(size_t)NBH*256*4*32];
__device__ uint2 g_KFl[(size_t)NBH*256*4*32];
// V fragment pack: idx = ((bh*8 + nv)*128 + jj)*32 + lane   [uint2]
__device__ uint2 g_VFh[(size_t)NBH*8*128*32];
__device__ uint2 g_VFl[(size_t)NBH*8*128*32];
// Projection A-frag pack: idx = (R*64 + c)*32 + lane        [uint4]
__device__ uint4 g_PAh[(size_t)(NM/16)*(NC/16)*32];
__device__ uint4 g_PAl[(size_t)(NM/16)*(NC/16)*32];
// Projection B-frag pack: idx = ((z*128 + n8)*64 + c)*32 + lane  [uint2]
__device__ uint2 g_PBh[(size_t)4*128*64*32];
__device__ uint2 g_PBl[(size_t)4*128*64*32];
// check scratch
__device__ float g_cm[8*16];
__device__ float g_cl[8*16];
__device__ float g_cacc[8*16*64];
__device__ int g_badF;   // tensor flash failed verification
__device__ int g_badP;   // tensor projection failed verification

// ---------------------------------------------------------------------------
// Helpers
// ---------------------------------------------------------------------------
__device__ __forceinline__ void mma_bf16(float* d, const uint32_t* a, const uint32_t* b) {
    asm volatile("mma.sync.aligned.m16n8k16.row.col.f32.bf16.bf16.f32 "
        "{%0,%1,%2,%3}, {%4,%5,%6,%7}, {%8,%9}, {%0,%1,%2,%3};"
        : "+f"(d[0]), "+f"(d[1]), "+f"(d[2]), "+f"(d[3])
        : "r"(a[0]), "r"(a[1]), "r"(a[2]), "r"(a[3]), "r"(b[0]), "r"(b[1]));
}
__device__ __forceinline__ void bsplit(float x, unsigned short& h, unsigned short& l) {
    __nv_bfloat16 bh = __float2bfloat16(x);
    float fh = __bfloat162float(bh);
    __nv_bfloat16 bl = __float2bfloat16(x - fh);
    h = __bfloat16_as_ushort(bh);
    l = __bfloat16_as_ushort(bl);
}
// pack two floats (low elem -> low 16 bits) into bf16x2 hi word + lo word
__device__ __forceinline__ uint32_t packP(float a, float b, uint32_t& lo) {
    unsigned short ha, la, hb, lb;
    bsplit(a, ha, la);
    bsplit(b, hb, lb);
    lo = (uint32_t)la | ((uint32_t)lb << 16);
    return (uint32_t)ha | ((uint32_t)hb << 16);
}

// ---------------------------------------------------------------------------
__global__ void zero_flag_kernel() { g_badF = 0; g_badP = 0; }

// ===========================================================================
// PROJECTION TENSOR PATH (R15-measured: QKV 178 us, tensor 71%)
// ===========================================================================

__global__ __launch_bounds__(256)
void pafrag_kernel(const float* __restrict__ xin, int src)
{
    const float* in = (src == 0) ? xin : g_Y;
    int idx = blockIdx.x * 256 + threadIdx.x;
    int lane = idx & 31;
    int Rc = idx >> 5;
    int c = Rc & 63, R = Rc >> 6;
    int g = lane >> 2, t = lane & 3;
    int r0 = R * 16 + g;
    int k0 = c * 16 + 2 * t;
    const float* p = in + (size_t)r0 * NC + k0;
    uint4 H, L;
    H.x = packP(p[0],          p[1],          L.x);
    H.y = packP(p[8 * NC],     p[8 * NC + 1], L.y);
    H.z = packP(p[8],          p[9],          L.z);
    H.w = packP(p[8 * NC + 8], p[8 * NC + 9], L.w);
    g_PAh[idx] = H;
    g_PAl[idx] = L;
}

__global__ __launch_bounds__(256)
void pbfrag_kernel(const float* __restrict__ Wq, const float* __restrict__ Wk,
                   const float* __restrict__ Wv, const float* __restrict__ Wo)
{
    int idx = blockIdx.x * 256 + threadIdx.x;
    int lane = idx & 31;
    int c = (idx >> 5) & 63;
    int n8 = (idx >> 11) & 127;
    int z = idx >> 18;
    const float* W = (z == 0) ? Wq : (z == 1) ? Wk : (z == 2) ? Wv : Wo;
    int g = lane >> 2, t = lane & 3;
    int n = n8 * 8 + g;
    int k0 = c * 16 + 2 * t;
    uint2 H, L;
    H.x = packP(W[(size_t)k0 * NC + n],       W[(size_t)(k0 + 1) * NC + n], L.x);
    H.y = packP(W[(size_t)(k0 + 8) * NC + n], W[(size_t)(k0 + 9) * NC + n], L.y);
    g_PBh[idx] = H;
    g_PBl[idx] = L;
}

// Fragment-packed bf16 GEMM, 32-row warp tile (256 rows/block).
__global__ __launch_bounds__(256)
void pgemm_kernel(const float* __restrict__ bq, const float* __restrict__ bk,
                  const float* __restrict__ bv, const float* __restrict__ bo,
                  float* __restrict__ Cext, int mode, int gate)
{
    if (gate && g_badP != 0) return;
    int tid = threadIdx.x, w = tid >> 5, lane = tid & 31;
    int g8 = lane >> 2, t4 = lane & 3;
    int n0 = blockIdx.x * 64, m0 = blockIdx.y * 256;
    int z = (mode == 0) ? blockIdx.z : 3;
    const float* bias = (mode == 0) ? ((z == 0) ? bq : (z == 1) ? bk : bv) : bo;
    float* C = (mode == 0) ? ((z == 0) ? g_Q : (z == 1) ? g_K : g_V) : Cext;

    int R0 = (m0 >> 4) + w * 2;
    const uint4* Ah0 = g_PAh + (size_t)R0 * 2048 + lane;
    const uint4* Al0 = g_PAl + (size_t)R0 * 2048 + lane;
    const uint4* Ah1 = g_PAh + (size_t)(R0 + 1) * 2048 + lane;
    const uint4* Al1 = g_PAl + (size_t)(R0 + 1) * 2048 + lane;
    const uint2* Bh = g_PBh + ((size_t)z * 128 + blockIdx.x * 8) * 2048 + lane;
    const uint2* Bl = g_PBl + ((size_t)z * 128 + blockIdx.x * 8) * 2048 + lane;

    float acc[2][8][4];
#pragma unroll
    for (int mf = 0; mf < 2; mf++)
#pragma unroll
        for (int nf = 0; nf < 8; nf++)
#pragma unroll
            for (int q = 0; q < 4; q++) acc[mf][nf][q] = 0.0f;

    for (int c = 0; c < 64; c++) {
        uint4 a4h0 = Ah0[c * 32];
        uint4 a4l0 = Al0[c * 32];
        uint4 a4h1 = Ah1[c * 32];
        uint4 a4l1 = Al1[c * 32];
        uint32_t ah[2][4], al[2][4];
        ah[0][0] = a4h0.x; ah[0][1] = a4h0.y; ah[0][2] = a4h0.z; ah[0][3] = a4h0.w;
        al[0][0] = a4l0.x; al[0][1] = a4l0.y; al[0][2] = a4l0.z; al[0][3] = a4l0.w;
        ah[1][0] = a4h1.x; ah[1][1] = a4h1.y; ah[1][2] = a4h1.z; ah[1][3] = a4h1.w;
        al[1][0] = a4l1.x; al[1][1] = a4l1.y; al[1][2] = a4l1.z; al[1][3] = a4l1.w;
#pragma unroll
        for (int nf = 0; nf < 8; nf++) {
            uint2 b2h = Bh[(size_t)nf * 2048 + c * 32];
            uint2 b2l = Bl[(size_t)nf * 2048 + c * 32];
            uint32_t bh[2], bl[2];
            bh[0] = b2h.x; bh[1] = b2h.y;
            bl[0] = b2l.x; bl[1] = b2l.y;
#pragma unroll
            for (int mf = 0; mf < 2; mf++) {
                mma_bf16(acc[mf][nf], ah[mf], bh);
                mma_bf16(acc[mf][nf], al[mf], bh);
                mma_bf16(acc[mf][nf], ah[mf], bl);
            }
        }
    }

#pragma unroll
    for (int mf = 0; mf < 2; mf++) {
        int mrow = m0 + (w * 2 + mf) * 16 + g8;
#pragma unroll
        for (int nf = 0; nf < 8; nf++) {
            int col = n0 + nf * 8 + t4 * 2;
            float2 b2 = *(const float2*)(bias + col);
            float2 o;
            o.x = acc[mf][nf][0] + b2.x; o.y = acc[mf][nf][1] + b2.y;
            *(float2*)(C + (size_t)mrow * NC + col) = o;
            o.x = acc[mf][nf][2] + b2.x; o.y = acc[mf][nf][3] + b2.y;
            *(float2*)(C + (size_t)(mrow + 8) * NC + col) = o;
        }
    }
}

__global__ __launch_bounds__(256)
void pcheck_kernel(const float* __restrict__ x, const float* __restrict__ W,
                   const float* __restrict__ b, int which)
{
    int idx = blockIdx.x * 256 + threadIdx.x;
    int r = idx >> 7, c = idx & 127;
    const float* xr = x + (size_t)r * NC;
    float s = 0.0f;
#pragma unroll 4
    for (int k = 0; k < NC; k++)
        s += xr[k] * W[(size_t)k * NC + c];
    s += b[c];
    const float* Cq = (which == 0) ? g_Q : (which == 1) ? g_K : g_V;
    float q = Cq[(size_t)r * NC + c];
    if (fabsf(q - s) > 0.02f * (fabsf(s) + 0.5f))
        atomicExch(&g_badP, 1);
}

// ===========================================================================
// FLASH TENSOR PATH (R13/R14-proven 32-key chunk version)
// ===========================================================================

__global__ __launch_bounds__(256)
void pack_q_kernel()
{
    int id = blockIdx.x * 256 + threadIdx.x;
    int d4 = id & 15;
    int t = (id >> 4) & (NT - 1);
    int bh = id >> 15;
    int b = bh >> 4, h = bh & 15;
    size_t src = ((size_t)(b * NT + t)) * NC + h * DH + d4 * 4;
    size_t dst = ((size_t)bh * NT + t) * DH + d4 * 4;
    float4 q = *(const float4*)(g_Q + src);
    ushort4 qh, ql;
    bsplit(q.x * 0.125f, qh.x, ql.x);
    bsplit(q.y * 0.125f, qh.y, ql.y);
    bsplit(q.z * 0.125f, qh.z, ql.z);
    bsplit(q.w * 0.125f, qh.w, ql.w);
    *(ushort4*)(g_Qbh + dst) = qh;
    *(ushort4*)(g_Qbl + dst) = ql;
}

__global__ __launch_bounds__(256)
void kfrag_kernel()
{
    int id = blockIdx.x * 256 + threadIdx.x;
    int lane = id & 31;
    int kc = (id >> 5) & 3;
    int k8 = (id >> 7) & 255;
    int bh = id >> 15;
    int b = bh >> 4, h = bh & 15;
    int g8 = lane >> 2, t4 = lane & 3;
    int key = k8 * 8 + g8;
    int d0 = kc * 16 + 2 * t4;
    const float* p = g_K + ((size_t)(b * NT + key)) * NC + h * DH + d0;
    uint2 H, L;
    H.x = packP(p[0], p[1], L.x);
    H.y = packP(p[8], p[9], L.y);
    g_KFh[id] = H;
    g_KFl[id] = L;
}

__global__ __launch_bounds__(256)
void vfrag_kernel()
{
    int id = blockIdx.x * 256 + threadIdx.x;
    int lane = id & 31;
    int jj = (id >> 5) & 127;
    int nv = (id >> 12) & 7;
    int bh = id >> 15;
    int b = bh >> 4, h = bh & 15;
    int g8 = lane >> 2, t4 = lane & 3;
    int d = nv * 8 + g8;
    int key0 = jj * 16 + 2 * t4;
    const float* base = g_V + (size_t)b * NT * NC + h * DH + d;
    uint2 H, L;
    H.x = packP(base[(size_t)key0 * NC],       base[(size_t)(key0 + 1) * NC], L.x);
    H.y = packP(base[(size_t)(key0 + 8) * NC], base[(size_t)(key0 + 9) * NC], L.y);
    g_VFh[id] = H;
    g_VFl[id] = L;
}

__global__ __launch_bounds__(128)
void flash_mma_kernel()
{
    int tid = threadIdx.x, w = tid >> 5, lane = tid & 31;
    int g8 = lane >> 2, t4 = lane & 3;
    int qt = blockIdx.x, bh = blockIdx.y;

    const unsigned short* Qh = g_Qbh + ((size_t)bh * NT + qt * 64 + w * 16) * DH;
    const unsigned short* Ql = g_Qbl + ((size_t)bh * NT + qt * 64 + w * 16) * DH;
    uint32_t qfh[4][4], qfl[4][4];
#pragma unroll
    for (int kc = 0; kc < 4; kc++) {
        int d0 = kc * 16 + 2 * t4;
        qfh[kc][0] = *(const uint32_t*)(Qh + (size_t)g8 * DH + d0);
        qfh[kc][1] = *(const uint32_t*)(Qh + (size_t)(g8 + 8) * DH + d0);
        qfh[kc][2] = *(const uint32_t*)(Qh + (size_t)g8 * DH + d0 + 8);
        qfh[kc][3] = *(const uint32_t*)(Qh + (size_t)(g8 + 8) * DH + d0 + 8);
        qfl[kc][0] = *(const uint32_t*)(Ql + (size_t)g8 * DH + d0);
        qfl[kc][1] = *(const uint32_t*)(Ql + (size_t)(g8 + 8) * DH + d0);
        qfl[kc][2] = *(const uint32_t*)(Ql + (size_t)g8 * DH + d0 + 8);
        qfl[kc][3] = *(const uint32_t*)(Ql + (size_t)(g8 + 8) * DH + d0 + 8);
    }

    const uint2* KFh = g_KFh + (size_t)bh * 32768 + lane;
    const uint2* KFl = g_KFl + (size_t)bh * 32768 + lane;
    const uint2* VFh = g_VFh + (size_t)bh * 32768 + lane;
    const uint2* VFl = g_VFl + (size_t)bh * 32768 + lane;

    float o[8][4];
#pragma unroll
    for (int nv = 0; nv < 8; nv++)
#pragma unroll
        for (int q = 0; q < 4; q++) o[nv][q] = 0.0f;
    float m0 = -1e30f, m1 = -1e30f, l0 = 0.0f, l1 = 0.0f;

    for (int k0 = 0; k0 < NT; k0 += 32) {
        int k8b = k0 >> 3;
        float s[4][4];
#pragma unroll
        for (int nf = 0; nf < 4; nf++)
#pragma unroll
            for (int q = 0; q < 4; q++) s[nf][q] = 0.0f;
#pragma unroll
        for (int nf = 0; nf < 4; nf++) {
            size_t kb = (size_t)(k8b + nf) * 128;
#pragma unroll
            for (int kc = 0; kc < 4; kc++) {
                uint2 kh = KFh[kb + kc * 32];
                uint2 kl = KFl[kb + kc * 32];
                uint32_t bhh[2], bll[2];
                bhh[0] = kh.x; bhh[1] = kh.y;
                bll[0] = kl.x; bll[1] = kl.y;
                mma_bf16(s[nf], qfh[kc], bhh);
                mma_bf16(s[nf], qfl[kc], bhh);
                mma_bf16(s[nf], qfh[kc], bll);
            }
        }

        {
            float rm = s[0][0];
#pragma unroll
            for (int nf = 0; nf < 4; nf++) {
                rm = fmaxf(rm, s[nf][0]);
                rm = fmaxf(rm, s[nf][1]);
            }
            rm = fmaxf(rm, __shfl_xor_sync(0xffffffffu, rm, 1));
            rm = fmaxf(rm, __shfl_xor_sync(0xffffffffu, rm, 2));
            float mn = fmaxf(m0, rm);
            float corr = __expf(m0 - mn);
            float rs = 0.0f;
#pragma unroll
            for (int nf = 0; nf < 4; nf++) {
                s[nf][0] = __expf(s[nf][0] - mn);
                s[nf][1] = __expf(s[nf][1] - mn);
                rs += s[nf][0] + s[nf][1];
            }
            rs += __shfl_xor_sync(0xffffffffu, rs, 1);
            rs += __shfl_xor_sync(0xffffffffu, rs, 2);
            l0 = l0 * corr + rs;
            m0 = mn;
#pragma unroll
            for (int nv = 0; nv < 8; nv++) {
                o[nv][0] *= corr;
                o[nv][1] *= corr;
            }
        }
        {
            float rm = s[0][2];
#pragma unroll
            for (int nf = 0; nf < 4; nf++) {
                rm = fmaxf(rm, s[nf][2]);
                rm = fmaxf(rm, s[nf][3]);
            }
            rm = fmaxf(rm, __shfl_xor_sync(0xffffffffu, rm, 1));
            rm = fmaxf(rm, __shfl_xor_sync(0xffffffffu, rm, 2));
            float mn = fmaxf(m1, rm);
            float corr = __expf(m1 - mn);
            float rs = 0.0f;
#pragma unroll
            for (int nf = 0; nf < 4; nf++) {
                s[nf][2] = __expf(s[nf][2] - mn);
                s[nf][3] = __expf(s[nf][3] - mn);
                rs += s[nf][2] + s[nf][3];
            }
            rs += __shfl_xor_sync(0xffffffffu, rs, 1);
            rs += __shfl_xor_sync(0xffffffffu, rs, 2);
            l1 = l1 * corr + rs;
            m1 = mn;
#pragma unroll
            for (int nv = 0; nv < 8; nv++) {
                o[nv][2] *= corr;
                o[nv][3] *= corr;
            }
        }

#pragma unroll
        for (int j = 0; j < 2; j++) {
            uint32_t ph[4], pl[4];
            ph[0] = packP(s[2 * j][0],     s[2 * j][1],     pl[0]);
            ph[1] = packP(s[2 * j][2],     s[2 * j][3],     pl[1]);
            ph[2] = packP(s[2 * j + 1][0], s[2 * j + 1][1], pl[2]);
            ph[3] = packP(s[2 * j + 1][2], s[2 * j + 1][3], pl[3]);
            int jbase = (k0 >> 4) + j;
#pragma unroll
            for (int nv = 0; nv < 8; nv++) {
                uint2 vh = VFh[((size_t)nv * 128 + jbase) * 32];
                uint2 vl = VFl[((size_t)nv * 128 + jbase) * 32];
                uint32_t bvh[2], bvl[2];
                bvh[0] = vh.x; bvh[1] = vh.y;
                bvl[0] = vl.x; bvl[1] = vl.y;
                mma_bf16(o[nv], ph, bvh);
                mma_bf16(o[nv], pl, bvh);
                mma_bf16(o[nv], ph, bvl);
            }
        }
    }

    float inv0 = 1.0f / l0, inv1 = 1.0f / l1;
    int b = bh >> 4, h = bh & 15;
    size_t row0 = (size_t)b * NT + qt * 64 + w * 16 + g8;
#pragma unroll
    for (int nv = 0; nv < 8; nv++) {
        int col = h * DH + nv * 8 + t4 * 2;
        float2 v;
        v.x = o[nv][0] * inv0; v.y = o[nv][1] * inv0;
        *(float2*)(g_Y + row0 * NC + col) = v;
        v.x = o[nv][2] * inv1; v.y = o[nv][3] * inv1;
        *(float2*)(g_Y + (row0 + 8) * NC + col) = v;
    }
}

__global__ __launch_bounds__(128)
void fcheck1_kernel()
{
    int sl = blockIdx.x;
    int tid = threadIdx.x;
    int r = tid >> 4, c = tid & 15;
    const float* Qr = g_Q + (size_t)r * NC;
    float m = -1e30f, l = 0.0f;
    float acc[4] = {0.0f, 0.0f, 0.0f, 0.0f};

    for (int key = sl * 128; key < sl * 128 + 128; key++) {
        const float* Kr = g_K + (size_t)key * NC;
        float part = 0.0f;
#pragma unroll
        for (int dd = 0; dd < 4; dd++) part += Qr[c * 4 + dd] * Kr[c * 4 + dd];
        part += __shfl_xor_sync(0xffffffffu, part, 1);
        part += __shfl_xor_sync(0xffffffffu, part, 2);
        part += __shfl_xor_sync(0xffffffffu, part, 4);
        part += __shfl_xor_sync(0xffffffffu, part, 8);
        float sc = part * 0.125f;
        float mn = fmaxf(m, sc);
        float corr = __expf(m - mn);
        float p = __expf(sc - mn);
        l = l * corr + p;
        const float* Vr = g_V + (size_t)key * NC;
#pragma unroll
        for (int dd = 0; dd < 4; dd++)
            acc[dd] = acc[dd] * corr + p * Vr[c * 4 + dd];
        m = mn;
    }
    if (c == 0) { g_cm[r * 16 + sl] = m; g_cl[r * 16 + sl] = l; }
#pragma unroll
    for (int dd = 0; dd < 4; dd++)
        g_cacc[(r * 16 + sl) * 64 + c * 4 + dd] = acc[dd];
}

__global__ __launch_bounds__(512)
void fcheck2_kernel()
{
    int tid = threadIdx.x;
    int r = tid >> 6, d = tid & 63;
    float M = -1e30f;
#pragma unroll
    for (int sl = 0; sl < 16; sl++) M = fmaxf(M, g_cm[r * 16 + sl]);
    float L = 0.0f, A = 0.0f;
#pragma unroll
    for (int sl = 0; sl < 16; sl++) {
        float e = __expf(g_cm[r * 16 + sl] - M);
        L += g_cl[r * 16 + sl] * e;
        A += g_cacc[(r * 16 + sl) * 64 + d] * e;
    }
    float y = A / L;
    float got = g_Y[(size_t)r * NC + d];
    if (fabsf(got - y) > 0.02f * fabsf(y) + 0.01f)
        atomicExch(&g_badF, 1);
}

// ===========================================================================
// FP32 FALLBACKS (proven R1 kernels, gated)
// ===========================================================================
#define GBM 128
#define GBN 128
#define GBK 8

__global__ __launch_bounds__(256)
void sgemm_bias_kernel(const float* __restrict__ Aext,
                       const float* __restrict__ W0, const float* __restrict__ W1,
                       const float* __restrict__ W2,
                       const float* __restrict__ b0, const float* __restrict__ b1,
                       const float* __restrict__ b2,
                       float* __restrict__ Cext, int mode)
{
    if (g_badP == 0) return;

    const int N = NC, K = NC;
    const float* A; const float* W; const float* bias; float* C;
    int z = blockIdx.z;
    if (mode == 0) {
        A = Aext;
        W    = (z == 0) ? W0 : (z == 1) ? W1 : W2;
        bias = (z == 0) ? b0 : (z == 1) ? b1 : b2;
        C    = (z == 0) ? g_Q : (z == 1) ? g_K : g_V;
    } else {
        A = g_Y; W = W0; bias = b0; C = Cext;
    }

    __shared__ float As[GBK][GBM];
    __shared__ float Bs[GBK][GBN];

    int tid = threadIdx.x;
    int bx = blockIdx.x, by = blockIdx.y;

    float acc[8][8];
#pragma unroll
    for (int i = 0; i < 8; i++)
#pragma unroll
        for (int j = 0; j < 8; j++) acc[i][j] = 0.0f;

    const float* Ab = A + (size_t)by * GBM * K;
    const float* Wb = W + (size_t)bx * GBN;

    int arow = tid >> 1, acol = (tid & 1) * 4;
    int brow = tid >> 5, bcol = (tid & 31) * 4;
    int rg = (tid >> 4) * 8;
    int cg = (tid & 15) * 8;

    for (int kt = 0; kt < K; kt += GBK) {
        float4 av = *(const float4*)(Ab + (size_t)arow * K + kt + acol);
        float4 bv = *(const float4*)(Wb + (size_t)(kt + brow) * N + bcol);
        __syncthreads();
        As[acol + 0][arow] = av.x;
        As[acol + 1][arow] = av.y;
        As[acol + 2][arow] = av.z;
        As[acol + 3][arow] = av.w;
        *(float4*)&Bs[brow][bcol] = bv;
        __syncthreads();
#pragma unroll
        for (int k = 0; k < GBK; k++) {
            float ra[8], rb[8];
            *(float4*)&ra[0] = *(const float4*)&As[k][rg];
            *(float4*)&ra[4] = *(const float4*)&As[k][rg + 4];
            *(float4*)&rb[0] = *(const float4*)&Bs[k][cg];
            *(float4*)&rb[4] = *(const float4*)&Bs[k][cg + 4];
#pragma unroll
            for (int i = 0; i < 8; i++)
#pragma unroll
                for (int j = 0; j < 8; j++)
                    acc[i][j] += ra[i] * rb[j];
        }
    }

    size_t row0 = (size_t)by * GBM + rg;
    int col0 = bx * GBN + cg;
#pragma unroll
    for (int i = 0; i < 8; i++) {
#pragma unroll
        for (int j = 0; j < 8; j += 4) {
            float4 o;
            o.x = acc[i][j + 0] + bias[col0 + j + 0];
            o.y = acc[i][j + 1] + bias[col0 + j + 1];
            o.z = acc[i][j + 2] + bias[col0 + j + 2];
            o.w = acc[i][j + 3] + bias[col0 + j + 3];
            *(float4*)(C + (row0 + i) * N + col0 + j) = o;
        }
    }
}

#define FBQ 64
#define FBK 32
#define QP 65
#define KP 66
#define SP 33

__global__ __launch_bounds__(128)
void flash_fp32_kernel()
{
    if (g_badF == 0) return;

    __shared__ float Qs[FBQ][QP];
    __shared__ float KS[2112];
    __shared__ float Vs[FBK][DH];

    int tid = threadIdx.x;
    int qt = blockIdx.x;
    int bh = blockIdx.y;
    int b = bh >> 4, h = bh & 15;

    const float* Qg = g_Q + (size_t)b * NT * NC + h * DH;
    const float* Kg = g_K + (size_t)b * NT * NC + h * DH;
    const float* Vg = g_V + (size_t)b * NT * NC + h * DH;

    int ty = tid >> 3;
    int tx = tid & 7;
    int ty4 = ty * 4;

    {
        int lq = tid >> 4;
        int d  = (tid & 15) * 4;
#pragma unroll
        for (int r = 0; r < 8; r++) {
            int q = lq + r * 8;
            float4 v = *(const float4*)(Qg + (size_t)(qt * FBQ + q) * NC + d);
            Qs[q][d + 0] = v.x * 0.125f;
            Qs[q][d + 1] = v.y * 0.125f;
            Qs[q][d + 2] = v.z * 0.125f;
            Qs[q][d + 3] = v.w * 0.125f;
        }
    }

    float oa[4][8];
    float m_r[4], l_r[4];
#pragma unroll
    for (int i = 0; i < 4; i++) {
        m_r[i] = -1e30f; l_r[i] = 0.0f;
#pragma unroll
        for (int c = 0; c < 8; c++) oa[i][c] = 0.0f;
    }

    for (int kt = 0; kt < NT / FBK; kt++) {
        const float* Kt = Kg + (size_t)(kt * FBK) * NC;
        const float* Vt = Vg + (size_t)(kt * FBK) * NC;

        __syncthreads();
        {
            int lk = tid >> 4;
            int d  = (tid & 15) * 4;
#pragma unroll
            for (int r = 0; r < 4; r++) {
                int key = lk + r * 8;
                float4 kv = *(const float4*)(Kt + (size_t)key * NC + d);
                float* Kp = &KS[key * KP + d];
                Kp[0] = kv.x; Kp[1] = kv.y; Kp[2] = kv.z; Kp[3] = kv.w;
                float4 vv = *(const float4*)(Vt + (size_t)key * NC + d);
                *(float4*)&Vs[key][d] = vv;
            }
        }
        __syncthreads();

        float s[4][4];
#pragma unroll
        for (int i = 0; i < 4; i++)
#pragma unroll
            for (int j = 0; j < 4; j++) s[i][j] = 0.0f;

#pragma unroll 4
        for (int d = 0; d < DH; d++) {
            float rq[4], rk[4];
#pragma unroll
            for (int i = 0; i < 4; i++) rq[i] = Qs[ty4 + i][d];
#pragma unroll
            for (int j = 0; j < 4; j++) rk[j] = KS[(tx + 8 * j) * KP + d];
#pragma unroll
            for (int i = 0; i < 4; i++)
#pragma unroll
                for (int j = 0; j < 4; j++)
                    s[i][j] += rq[i] * rk[j];
        }
        __syncthreads();

        float p[4][4], corr[4], rsum[4];
#pragma unroll
        for (int i = 0; i < 4; i++) {
            float tm = fmaxf(fmaxf(s[i][0], s[i][1]), fmaxf(s[i][2], s[i][3]));
            tm = fmaxf(tm, __shfl_xor_sync(0xffffffffu, tm, 1));
            tm = fmaxf(tm, __shfl_xor_sync(0xffffffffu, tm, 2));
            tm = fmaxf(tm, __shfl_xor_sync(0xffffffffu, tm, 4));
            float mnew = fmaxf(m_r[i], tm);
            corr[i] = __expf(m_r[i] - mnew);
            float rs = 0.0f;
#pragma unroll
            for (int j = 0; j < 4; j++) {
                p[i][j] = __expf(s[i][j] - mnew);
                rs += p[i][j];
            }
            rs += __shfl_xor_sync(0xffffffffu, rs, 1);
            rs += __shfl_xor_sync(0xffffffffu, rs, 2);
            rs += __shfl_xor_sync(0xffffffffu, rs, 4);
            rsum[i] = rs;
            m_r[i] = mnew;
        }
#pragma unroll
        for (int i = 0; i < 4; i++) {
            l_r[i] = l_r[i] * corr[i] + rsum[i];
#pragma unroll
            for (int c = 0; c < 8; c++) oa[i][c] *= corr[i];
        }

#pragma unroll
        for (int i = 0; i < 4; i++)
#pragma unroll
            for (int j = 0; j < 4; j++)
                KS[(ty4 + i) * SP + (tx + 8 * j)] = p[i][j];
        __syncthreads();

#pragma unroll 4
        for (int k = 0; k < FBK; k++) {
            float rs[4];
#pragma unroll
            for (int i = 0; i < 4; i++) rs[i] = KS[(ty4 + i) * SP + k];
            float4 v0 = *(const float4*)&Vs[k][tx * 8];
            float4 v1 = *(const float4*)&Vs[k][tx * 8 + 4];
#pragma unroll
            for (int i = 0; i < 4; i++) {
                oa[i][0] += rs[i] * v0.x;
                oa[i][1] += rs[i] * v0.y;
                oa[i][2] += rs[i] * v0.z;
                oa[i][3] += rs[i] * v0.w;
                oa[i][4] += rs[i] * v1.x;
                oa[i][5] += rs[i] * v1.y;
                oa[i][6] += rs[i] * v1.z;
                oa[i][7] += rs[i] * v1.w;
            }
        }
    }

#pragma unroll
    for (int i = 0; i < 4; i++) {
        float inv = 1.0f / l_r[i];
        size_t row = (size_t)b * NT + qt * FBQ + ty4 + i;
        float* Yp = g_Y + row * NC + h * DH + tx * 8;
        float4 o0, o1;
        o0.x = oa[i][0] * inv; o0.y = oa[i][1] * inv;
        o0.z = oa[i][2] * inv; o0.w = oa[i][3] * inv;
        o1.x = oa[i][4] * inv; o1.y = oa[i][5] * inv;
        o1.z = oa[i][6] * inv; o1.w = oa[i][7] * inv;
        *(float4*)Yp = o0;
        *(float4*)(Yp + 4) = o1;
    }
}

// ---------------------------------------------------------------------------
extern "C" void kernel_launch(void* const* d_in, const int* in_sizes, int n_in,
                              void* d_out, int out_size)
{
    const float* x  = (const float*)d_in[0];
    const float* Wq = (const float*)d_in[1];
    const float* bq = (const float*)d_in[2];
    const float* Wk = (const float*)d_in[3];
    const float* bk = (const float*)d_in[4];
    const float* Wv = (const float*)d_in[5];
    const float* bv = (const float*)d_in[6];
    const float* Wo = (const float*)d_in[7];
    const float* bo = (const float*)d_in[8];
    float* out = (float*)d_out;

    // 0) reset flags
    zero_flag_kernel<<<1, 1>>>();
    // 1) projection fragment packs (x + all weights)
    pafrag_kernel<<<(NM / 16) * (NC / 16) * 32 / 256, 256>>>(x, 0);
    pbfrag_kernel<<<4 * 128 * 64 * 32 / 256, 256>>>(Wq, Wk, Wv, Wo);
    // 2) tensor QKV projections (256 rows/block)
    pgemm_kernel<<<dim3(NC / 64, NM / 256, 3), 256>>>(
        bq, bk, bv, bo, nullptr, 0, 0);
    // 3) verify Q, K, V tiles
    pcheck_kernel<<<16, 256>>>(x, Wq, bq, 0);
    pcheck_kernel<<<16, 256>>>(x, Wk, bk, 1);
    pcheck_kernel<<<16, 256>>>(x, Wv, bv, 2);
    // 4) fp32 fallback QKV (no-op when verified)
    sgemm_bias_kernel<<<dim3(NC / GBN, NM / GBM, 3), 256>>>(
        x, Wq, Wk, Wv, bq, bk, bv, nullptr, 0);
    // 5) flash packs + tensor flash (32-key chunk, R13/R14-proven)
    pack_q_kernel<<<4096, 256>>>();
    kfrag_kernel<<<4096, 256>>>();
    vfrag_kernel<<<4096, 256>>>();
    flash_mma_kernel<<<dim3(NT / 64, NBH), 128>>>();
    // 6) flash verification + fp32 fallback
    fcheck1_kernel<<<16, 128>>>();
    fcheck2_kernel<<<1, 512>>>();
    flash_fp32_kernel<<<dim3(NT / FBQ, NBH), 128>>>();
    // 7) out-projection: pack Y, tensor gemm (gated) / fp32 fallback
    pafrag_kernel<<<(NM / 16) * (NC / 16) * 32 / 256, 256>>>(x, 1);
    pgemm_kernel<<<dim3(NC / 64, NM / 256, 1), 256>>>(
        bq, bk, bv, bo, out, 1, 1);
    sgemm_bias_kernel<<<dim3(NC / GBN, NM / GBM, 1), 256>>>(
        x, Wo, nullptr, nullptr, bo, nullptr, nullptr, out, 1);
}